// round 16
// baseline (speedup 1.0000x reference)
#include <cuda_runtime.h>
#include <math.h>

#define SEQ  32768
#define HID  1024
#define RPB  8                  // rows per block (one per warp)
#define NB   (SEQ / RPB)        // 4096 matvec blocks
#define NRM_THREADS 512
#define NRM_BLOCKS  (SEQ / NRM_THREADS)

// Scratch (no device allocation allowed). g_energies fully rewritten every
// call. g_M/g_S/g_done are reset to these exact values by the last
// normalize block each call -> every graph replay sees identical state.
__device__ float    g_energies[SEQ];
__device__ unsigned g_M    = 0u;    // global max, monotonic-mapped float bits
__device__ double   g_S    = 0.0;   // global sum of exp(e) (double, no shift)
__device__ unsigned g_done = 0u;

// Monotonic unsigned mapping for float atomicMax (exact, order-independent)
__device__ __forceinline__ unsigned fmap(float f) {
    unsigned b = __float_as_uint(f);
    return b ^ ((b & 0x80000000u) ? 0xFFFFFFFFu : 0x80000000u);
}
__device__ __forceinline__ float funmap(unsigned m) {
    unsigned b = (m & 0x80000000u) ? (m ^ 0x80000000u) : ~m;
    return __uint_as_float(b);
}

// ---------------------------------------------------------------------------
// Kernel 1: energies[row] = dot(enc[row,:], hidden). Block contributes its
// max (exact atomicMax) and sum-of-exp (double atomicAdd) to global scalars;
// both atomics hide under the 22us HBM-bound phase.
// ---------------------------------------------------------------------------
__global__ __launch_bounds__(256) void matvec_kernel(
    const float* __restrict__ hidden,
    const float* __restrict__ enc)
{
    __shared__ float4 sh_h[HID / 4];  // 4 KB
    __shared__ float  sh_e[RPB];

    int tid = threadIdx.x;
    sh_h[tid] = reinterpret_cast<const float4*>(hidden)[tid];
    __syncthreads();

    int warp = tid >> 5;
    int lane = tid & 31;
    int row  = blockIdx.x * RPB + warp;

    const float4* e4 = reinterpret_cast<const float4*>(enc)
                     + (size_t)row * (HID / 4);

    float acc = 0.0f;
#pragma unroll
    for (int i = 0; i < 8; i++) {
        float4 a = __ldcs(e4 + i * 32 + lane);   // streaming: read-once data
        float4 h = sh_h[i * 32 + lane];
        acc = fmaf(a.x, h.x, acc);
        acc = fmaf(a.y, h.y, acc);
        acc = fmaf(a.z, h.z, acc);
        acc = fmaf(a.w, h.w, acc);
    }

#pragma unroll
    for (int o = 16; o; o >>= 1)
        acc += __shfl_xor_sync(0xffffffffu, acc, o);

    if (lane == 0) {
        g_energies[row] = acc;
        sh_e[warp] = acc;
    }
    __syncthreads();

    // lanes 0..7 of warp 0: block max + block sum(exp) -> 2 atomics/block
    if (tid < RPB) {
        float e = sh_e[tid];
        float m = e;
#pragma unroll
        for (int o = RPB / 2; o; o >>= 1)
            m = fmaxf(m, __shfl_xor_sync(0xffu, m, o));
        double p = exp((double)e);   // |e| << 709: cannot overflow
#pragma unroll
        for (int o = RPB / 2; o; o >>= 1)
            p += __shfl_xor_sync(0xffu, p, o);
        if (tid == 0) {
            atomicMax(&g_M, fmap(m));
            atomicAdd(&g_S, p);
        }
    }

    cudaTriggerProgrammaticLaunchCompletion();
}

// ---------------------------------------------------------------------------
// Kernel 2 (PDL secondary): reads TWO scalars, one expf + store per element.
// Last block resets global state for the next call/replay.
// ---------------------------------------------------------------------------
__global__ __launch_bounds__(NRM_THREADS) void normalize_kernel(
    float* __restrict__ out)
{
    __shared__ float shM, shC;

    int tid = threadIdx.x;

    cudaGridDependencySynchronize();   // all matvec writes/atomics visible

    if (tid == 0) {
        float  M = funmap(g_M);
        double S = g_S;
        shM = M;
        // softmax: exp(e)/S = expf(e - M) * (exp(M)/S); one double exp/block
        shC = (float)(exp((double)M) / S);
    }
    __syncthreads();
    const float M = shM, C = shC;

    int i = blockIdx.x * NRM_THREADS + tid;
    out[i] = __expf(g_energies[i] - M) * C;

    // Reset protocol: every block's tid0 has finished reading the scalars
    // (before the first __syncthreads). Last arriver restores the zeros.
    if (tid == 0) {
        unsigned o = atomicAdd(&g_done, 1u);
        if (o == (unsigned)(NRM_BLOCKS - 1)) {
            g_M    = 0u;
            g_S    = 0.0;
            g_done = 0u;
            __threadfence();
        }
    }
}

// ---------------------------------------------------------------------------
extern "C" void kernel_launch(void* const* d_in, const int* in_sizes, int n_in,
                              void* d_out, int out_size)
{
    const float* hidden = (const float*)d_in[0];   // [1024]
    const float* enc    = (const float*)d_in[1];   // [32768, 1024]
    float* out          = (float*)d_out;           // [1,1,32768]

    matvec_kernel<<<NB, 256>>>(hidden, enc);

    // PDL launch: normalize dispatches during matvec and self-syncs on its
    // completion, hiding launch latency (and ramp, where residency allows).
    cudaLaunchConfig_t cfg = {};
    cfg.gridDim  = dim3(NRM_BLOCKS);
    cfg.blockDim = dim3(NRM_THREADS);
    cudaLaunchAttribute attrs[1];
    attrs[0].id = cudaLaunchAttributeProgrammaticStreamSerialization;
    attrs[0].val.programmaticStreamSerializationAllowed = 1;
    cfg.attrs    = attrs;
    cfg.numAttrs = 1;
    cudaError_t e = cudaLaunchKernelEx(&cfg, normalize_kernel, out);
    if (e != cudaSuccess) {
        normalize_kernel<<<NRM_BLOCKS, NRM_THREADS>>>(out);  // fallback
    }
}